// round 13
// baseline (speedup 1.0000x reference)
#include <cuda_runtime.h>
#include <cstdint>

#define N_NODES 50000
#define M_PAD   50048            // 391 * 128
#define N_EDGES 200000
#define DIM     384
#define XD      384
#define AGD     768
#define LK      1152             // logical K: [x | agg0 | agg1]
#define NREL    2

#define TM 128
#define TN 64
#define KC 64
#define NCHUNK 18               // LK / KC
#define MTILES 391
#define PRB 80                  // 64B int8 row + 16B pad (conflict-free ldsm)

// per-stage smem layout (bytes)
#define SA1 0
#define SA2 10240
#define SB1 20480
#define SB2 25600
#define STAGE_BYTES 30720
#define SMEM_TOTAL  61440

// ---------------- device scratch ----------------
__device__ __align__(16) int8_t g_xq1[(size_t)M_PAD * XD];
__device__ __align__(16) int8_t g_xq2[(size_t)M_PAD * XD];
__device__ __align__(16) int8_t g_aq1[(size_t)M_PAD * AGD];
__device__ __align__(16) int8_t g_aq2[(size_t)M_PAD * AGD];
__device__ __align__(16) int8_t g_wq1[(size_t)3 * DIM * LK];   // [L][n][k]
__device__ __align__(16) int8_t g_wq2[(size_t)3 * DIM * LK];
__device__ float g_wscale[3 * DIM];
__device__ __align__(16) float g_hf[(size_t)M_PAD * XD];
__device__ int   g_amax[3];               // bit-pattern of max|A| per layer input
__device__ int   g_cnt[N_NODES * NREL];
__device__ int   g_cur[N_NODES];
__device__ int   g_off[N_NODES + 1];
__device__ int   g_psrc[N_EDGES];         // src * XD
__device__ float g_pscale[N_EDGES];       // +s rel0, -s rel1

// ---------------- helpers ----------------
__device__ __forceinline__ uint32_t smem_u32(const void* p) {
    uint32_t a;
    asm("{ .reg .u64 t; cvta.to.shared.u64 t, %1; cvt.u32.u64 %0, t; }" : "=r"(a) : "l"(p));
    return a;
}
#define LDSM_X4(r, a)                                                                   \
    asm volatile("ldmatrix.sync.aligned.m8n8.x4.shared.b16 {%0,%1,%2,%3}, [%4];"        \
        : "=r"((r)[0]), "=r"((r)[1]), "=r"((r)[2]), "=r"((r)[3]) : "r"(a))
#define CP_ASYNC16(dst, src) \
    asm volatile("cp.async.cg.shared.global [%0], [%1], 16;" :: "r"(dst), "l"(src))
#define CP_COMMIT()  asm volatile("cp.async.commit_group;" ::: "memory")
#define CP_WAIT1()   asm volatile("cp.async.wait_group 1;" ::: "memory")
#define CP_WAIT0()   asm volatile("cp.async.wait_group 0;" ::: "memory")

#define IMMA(d, a, b0v, b1v)                                                            \
    asm volatile("mma.sync.aligned.m16n8k32.row.col.s32.s8.s8.s32 "                     \
        "{%0,%1,%2,%3}, {%4,%5,%6,%7}, {%8,%9}, {%0,%1,%2,%3};"                         \
        : "+r"((d)[0]), "+r"((d)[1]), "+r"((d)[2]), "+r"((d)[3])                        \
        : "r"((a)[0]), "r"((a)[1]), "r"((a)[2]), "r"((a)[3]), "r"(b0v), "r"(b1v))

__device__ __forceinline__ void q2i(float u, int8_t& o1, int8_t& o2) {
    float r1 = rintf(u);
    r1 = fminf(fmaxf(r1, -127.f), 127.f);
    float r2 = rintf((u - r1) * 128.f);
    r2 = fminf(fmaxf(r2, -127.f), 127.f);
    o1 = (int8_t)(int)r1;
    o2 = (int8_t)(int)r2;
}

struct i8x4 { int8_t x, y, z, w; };

// ---------------- edge preprocessing ----------------
__global__ void zero_kernel() {
    int i = blockIdx.x * blockDim.x + threadIdx.x;
    if (i < N_NODES * NREL) g_cnt[i] = 0;
    if (i < N_NODES) g_cur[i] = 0;
    if (i < 3) g_amax[i] = 0;
}
__device__ __forceinline__ int clampi(int v, int hi) {
    v = v < 0 ? 0 : v;
    return v >= hi ? hi - 1 : v;
}
__global__ void count_kernel(const int* __restrict__ ei, const int* __restrict__ et) {
    int e = blockIdx.x * blockDim.x + threadIdx.x;
    if (e >= N_EDGES) return;
    atomicAdd(&g_cnt[clampi(ei[N_EDGES + e], N_NODES) * NREL + clampi(et[e], NREL)], 1);
}
__global__ void scan2_kernel() {
    __shared__ int wsum[32];
    __shared__ int s_carry;
    const int tid = threadIdx.x;
    const int lane = tid & 31, w = tid >> 5;
    if (tid == 0) s_carry = 0;
    __syncthreads();
    for (int base = 0; base < N_NODES; base += 1024) {
        int i = base + tid;
        int v = (i < N_NODES) ? (g_cnt[i * NREL] + g_cnt[i * NREL + 1]) : 0;
        int incl = v;
#pragma unroll
        for (int o = 1; o < 32; o <<= 1) {
            int n = __shfl_up_sync(0xFFFFFFFF, incl, o);
            if (lane >= o) incl += n;
        }
        if (lane == 31) wsum[w] = incl;
        __syncthreads();
        if (w == 0) {
            int s = wsum[lane];
#pragma unroll
            for (int o = 1; o < 32; o <<= 1) {
                int n = __shfl_up_sync(0xFFFFFFFF, s, o);
                if (lane >= o) s += n;
            }
            wsum[lane] = s;
        }
        __syncthreads();
        int blk_excl = incl - v + (w > 0 ? wsum[w - 1] : 0);
        if (i < N_NODES) g_off[i] = s_carry + blk_excl;
        __syncthreads();
        if (tid == 0) s_carry += wsum[31];
        __syncthreads();
    }
    if (tid == 0) g_off[N_NODES] = s_carry;
}
__global__ void permute_kernel(const int* __restrict__ ei, const int* __restrict__ et) {
    int e = blockIdx.x * blockDim.x + threadIdx.x;
    if (e >= N_EDGES) return;
    int src = clampi(ei[e], N_NODES);
    int dst = clampi(ei[N_EDGES + e], N_NODES);
    int r   = clampi(et[e], NREL);
    int slot = g_off[dst] + atomicAdd(&g_cur[dst], 1);
    g_psrc[slot] = src * XD;
    int c = g_cnt[dst * NREL + r];
    float s = 1.0f / (float)(c > 0 ? c : 1);
    g_pscale[slot] = (r == 0) ? s : -s;
}

// ---------------- max|emb| ----------------
__global__ void maxabs_kernel(const float* __restrict__ e) {
    __shared__ float red[8];
    float m = 0.f;
    for (size_t i4 = ((size_t)blockIdx.x * 256 + threadIdx.x) * 4;
         i4 < (size_t)N_NODES * XD; i4 += (size_t)gridDim.x * 1024) {
        float4 v = *(const float4*)(e + i4);
        m = fmaxf(m, fmaxf(fmaxf(fabsf(v.x), fabsf(v.y)), fmaxf(fabsf(v.z), fabsf(v.w))));
    }
#pragma unroll
    for (int o = 16; o > 0; o >>= 1)
        m = fmaxf(m, __shfl_xor_sync(0xFFFFFFFF, m, o));
    if ((threadIdx.x & 31) == 0) red[threadIdx.x >> 5] = m;
    __syncthreads();
    if (threadIdx.x == 0) {
        float t = red[0];
#pragma unroll
        for (int i = 1; i < 8; i++) t = fmaxf(t, red[i]);
        atomicMax(&g_amax[0], __float_as_int(t));
    }
}

// ---------------- quantize x -> g_xq1/2; src chosen DEVICE-side (no symbol passing) ----------------
__global__ void quantx_kernel(const float* __restrict__ ext, int use_hf, int layer) {
    size_t i4 = ((size_t)blockIdx.x * blockDim.x + threadIdx.x) * 4;
    if (i4 >= (size_t)M_PAD * XD) return;
    const float* src = use_hf ? g_hf : ext;
    int row = (int)(i4 / XD);
    i8x4 o1 = {0, 0, 0, 0}, o2 = {0, 0, 0, 0};
    if (row < N_NODES) {
        float mx = __int_as_float(g_amax[layer]);
        float inv = (mx > 0.f) ? 127.f / mx : 0.f;
        float4 v = *(const float4*)(src + i4);
        q2i(v.x * inv, o1.x, o2.x);
        q2i(v.y * inv, o1.y, o2.y);
        q2i(v.z * inv, o1.z, o2.z);
        q2i(v.w * inv, o1.w, o2.w);
    }
    *(i8x4*)(g_xq1 + i4) = o1;
    *(i8x4*)(g_xq2 + i4) = o2;
}

// ---------------- weight quantization: per (L, n) column scale ----------------
__global__ void convert_w_kernel(const float* __restrict__ W1, const float* __restrict__ r1,
                                 const float* __restrict__ W2, const float* __restrict__ r2,
                                 const float* __restrict__ W3, const float* __restrict__ r3) {
    __shared__ float red[4];
    __shared__ float s_t;
    const int b = blockIdx.x;            // 0..1151
    const int L = b / DIM, n = b % DIM;
    const int tid = threadIdx.x;
    const float* root = (L == 0) ? r1 : (L == 1) ? r2 : r3;
    const float* Wr   = (L == 0) ? W1 : (L == 1) ? W2 : W3;

    float mx = 0.f;
    for (int k = tid; k < LK; k += 128) {
        float v = (k < XD) ? root[(size_t)k * DIM + n]
                           : Wr[(size_t)((k - XD) / DIM) * DIM * DIM
                                + (size_t)((k - XD) % DIM) * DIM + n];
        mx = fmaxf(mx, fabsf(v));
    }
#pragma unroll
    for (int o = 16; o > 0; o >>= 1)
        mx = fmaxf(mx, __shfl_xor_sync(0xFFFFFFFF, mx, o));
    if ((tid & 31) == 0) red[tid >> 5] = mx;
    __syncthreads();
    if (tid == 0) {
        float t = fmaxf(fmaxf(red[0], red[1]), fmaxf(red[2], red[3])) / 127.f;
        s_t = t;
        g_wscale[b] = t;
    }
    __syncthreads();
    float inv = (s_t > 0.f) ? 1.f / s_t : 0.f;
    for (int k = tid; k < LK; k += 128) {
        float v = (k < XD) ? root[(size_t)k * DIM + n]
                           : Wr[(size_t)((k - XD) / DIM) * DIM * DIM
                                + (size_t)((k - XD) % DIM) * DIM + n];
        int8_t a, c;
        q2i(v * inv, a, c);
        g_wq1[(size_t)b * LK + k] = a;
        g_wq2[(size_t)b * LK + k] = c;
    }
}

// ---------------- CSR gather in s-units: agg = sum w*(q1+q2/128), requantize ----------------
__global__ __launch_bounds__(96) void gather_kernel() {
    const int d = blockIdx.x;
    const int c = threadIdx.x * 4;
    const int beg = g_off[d], end = g_off[d + 1];
    const float kk = 0.0078125f;   // 1/128

    float4 a0 = make_float4(0.f, 0.f, 0.f, 0.f);
    float4 a1 = make_float4(0.f, 0.f, 0.f, 0.f);
    for (int j = beg; j < end; j++) {
        float s = g_pscale[j];
        int off = g_psrc[j] + c;
        i8x4 q1 = *(const i8x4*)(g_xq1 + off);
        i8x4 q2 = *(const i8x4*)(g_xq2 + off);
        float vx = (float)q1.x + (float)q2.x * kk;
        float vy = (float)q1.y + (float)q2.y * kk;
        float vz = (float)q1.z + (float)q2.z * kk;
        float vw = (float)q1.w + (float)q2.w * kk;
        if (s > 0.f) {
            a0.x += s * vx; a0.y += s * vy; a0.z += s * vz; a0.w += s * vw;
        } else {
            a1.x -= s * vx; a1.y -= s * vy; a1.z -= s * vz; a1.w -= s * vw;
        }
    }
    const size_t base = (size_t)d * AGD;
    i8x4 o1, o2;
    q2i(a0.x, o1.x, o2.x); q2i(a0.y, o1.y, o2.y);
    q2i(a0.z, o1.z, o2.z); q2i(a0.w, o1.w, o2.w);
    *(i8x4*)(g_aq1 + base + c) = o1;
    *(i8x4*)(g_aq2 + base + c) = o2;
    q2i(a1.x, o1.x, o2.x); q2i(a1.y, o1.y, o2.y);
    q2i(a1.z, o1.z, o2.z); q2i(a1.w, o1.w, o2.w);
    *(i8x4*)(g_aq1 + base + XD + c) = o1;
    *(i8x4*)(g_aq2 + base + XD + c) = o2;
}

// ---------------- int8 GEMM: two sweeps (P11, Pmid), fp32 merge ----------------
__device__ __forceinline__ void issue_chunk8(
    uint32_t sb, const int8_t* __restrict__ wq1, const int8_t* __restrict__ wq2,
    int row0, int n0, int k0, int tid)
{
    const bool inx = (k0 < XD);
    const int8_t* a1 = inx ? g_xq1 : g_aq1;
    const int8_t* a2 = inx ? g_xq2 : g_aq2;
    const int astr = inx ? XD : AGD;
    const int ak0 = inx ? k0 : k0 - XD;
#pragma unroll
    for (int i = 0; i < 6; i++) {
        int u = tid + i * 256;
        const int8_t* src;
        uint32_t dst;
        if (u < 1024) {
            int word = u >> 9, rem = u & 511;
            int row = rem >> 2, un = (rem & 3) * 16;
            src = (word ? a2 : a1) + (size_t)(row0 + row) * astr + ak0 + un;
            dst = sb + (word ? SA2 : SA1) + row * PRB + un;
        } else {
            int rem = u - 1024;
            int word = rem >> 8, rem2 = rem & 255;
            int row = rem2 >> 2, un = (rem2 & 3) * 16;
            src = (word ? wq2 : wq1) + (size_t)(n0 + row) * LK + k0 + un;
            dst = sb + (word ? SB2 : SB1) + row * PRB + un;
        }
        CP_ASYNC16(dst, src);
    }
    CP_COMMIT();
}

__global__ __launch_bounds__(256, 2) void gemm_imma_kernel(
    int layer, const float* __restrict__ bias,
    float* __restrict__ dout, int last)
{
    extern __shared__ char smem[];
    const uint32_t sbase = smem_u32(smem);
    const int tid = threadIdx.x;
    const int wid = tid >> 5, lane = tid & 31;
    const int row0 = blockIdx.x * TM;
    const int n0 = blockIdx.y * TN;

    const int8_t* wq1 = g_wq1 + (size_t)layer * DIM * LK;
    const int8_t* wq2 = g_wq2 + (size_t)layer * DIM * LK;

    const int wr = (wid >> 1) * 32;
    const int wc = (wid & 1) * 32;
    const int lrow = lane & 15;
    const int kb16 = (lane >> 4) * 16;

    float facc[32];
#pragma unroll
    for (int i = 0; i < 32; i++) facc[i] = 0.f;
    int iacc[32];

#pragma unroll 1
    for (int sweep = 0; sweep < 2; sweep++) {
#pragma unroll
        for (int i = 0; i < 32; i++) iacc[i] = 0;

        issue_chunk8(sbase, wq1, wq2, row0, n0, 0, tid);
        for (int c = 0; c < NCHUNK; c++) {
            if (c + 1 < NCHUNK) {
                issue_chunk8(sbase + ((c + 1) & 1) * STAGE_BYTES, wq1, wq2,
                             row0, n0, (c + 1) * KC, tid);
                CP_WAIT1();
            } else {
                CP_WAIT0();
            }
            __syncthreads();
            const uint32_t stg = sbase + (c & 1) * STAGE_BYTES;
#pragma unroll
            for (int ks = 0; ks < 2; ks++) {
                const int kb = ks * 32 + kb16;
                if (sweep == 0) {
                    uint32_t a1[2][4], b1[2][4];
#pragma unroll
                    for (int mt = 0; mt < 2; mt++)
                        LDSM_X4(a1[mt], stg + SA1 + (wr + mt * 16 + lrow) * PRB + kb);
#pragma unroll
                    for (int g2 = 0; g2 < 2; g2++)
                        LDSM_X4(b1[g2], stg + SB1 + (wc + g2 * 16 + lrow) * PRB + kb);
#pragma unroll
                    for (int mt = 0; mt < 2; mt++)
#pragma unroll
                        for (int g = 0; g < 4; g++)
                            IMMA(&iacc[(mt * 4 + g) * 4], a1[mt],
                                 b1[g >> 1][g & 1], b1[g >> 1][(g & 1) + 2]);
                } else {
                    uint32_t a1[2][4], a2[2][4], b1[2][4], b2[2][4];
#pragma unroll
                    for (int mt = 0; mt < 2; mt++) {
                        const uint32_t ra = (wr + mt * 16 + lrow) * PRB + kb;
                        LDSM_X4(a1[mt], stg + SA1 + ra);
                        LDSM_X4(a2[mt], stg + SA2 + ra);
                    }
#pragma unroll
                    for (int g2 = 0; g2 < 2; g2++) {
                        const uint32_t rb = (wc + g2 * 16 + lrow) * PRB + kb;
                        LDSM_X4(b1[g2], stg + SB1 + rb);
                        LDSM_X4(b2[g2], stg + SB2 + rb);
                    }
#pragma unroll
                    for (int mt = 0; mt < 2; mt++)
#pragma unroll
                        for (int g = 0; g < 4; g++) {
                            int* d = &iacc[(mt * 4 + g) * 4];
                            IMMA(d, a1[mt], b2[g >> 1][g & 1], b2[g >> 1][(g & 1) + 2]);
                            IMMA(d, a2[mt], b1[g >> 1][g & 1], b1[g >> 1][(g & 1) + 2]);
                        }
                }
            }
            __syncthreads();
        }
        if (sweep == 0) {
#pragma unroll
            for (int i = 0; i < 32; i++) facc[i] = (float)iacc[i];
        } else {
#pragma unroll
            for (int i = 0; i < 32; i++) facc[i] += (float)iacc[i] * 0.0078125f;
        }
    }

    // ---- epilogue ----
    const float s = __int_as_float(g_amax[layer]) * (1.f / 127.f);
    const int qr = lane >> 2, qc = (lane & 3) * 2;
    float wmax = 0.f;
#pragma unroll
    for (int mt = 0; mt < 2; mt++) {
#pragma unroll
        for (int g = 0; g < 4; g++) {
            const float* d = &facc[(mt * 4 + g) * 4];
            int m0 = row0 + wr + mt * 16 + qr;
            int n = n0 + wc + g * 8 + qc;
            float2 tt = *(const float2*)(g_wscale + layer * DIM + n);
            float2 bb = *(const float2*)(bias + n);
#pragma unroll
            for (int h = 0; h < 2; h++) {
                int m = m0 + h * 8;
                if (m >= N_NODES) continue;
                float x = s * tt.x * d[h * 2 + 0] + bb.x;
                float y = s * tt.y * d[h * 2 + 1] + bb.y;
                if (last) {
                    *(float2*)(dout + (size_t)m * DIM + n) = make_float2(x, y);
                } else {
                    x = fmaxf(x, 0.f);
                    y = fmaxf(y, 0.f);
                    wmax = fmaxf(wmax, fmaxf(x, y));
                    *(float2*)(g_hf + (size_t)m * XD + n) = make_float2(x, y);
                }
            }
        }
    }
    if (!last) {
#pragma unroll
        for (int o = 16; o > 0; o >>= 1)
            wmax = fmaxf(wmax, __shfl_xor_sync(0xFFFFFFFF, wmax, o));
        float* red = (float*)smem;
        if (lane == 0) red[wid] = wmax;
        __syncthreads();
        if (tid == 0) {
            float t = red[0];
#pragma unroll
            for (int i = 1; i < 8; i++) t = fmaxf(t, red[i]);
            atomicMax(&g_amax[layer + 1], __float_as_int(t));
        }
    }
}

// ---------------- launch ----------------
extern "C" void kernel_launch(void* const* d_in, const int* in_sizes, int n_in,
                              void* d_out, int out_size)
{
    const float* emb = (const float*)d_in[0];
    const int*   ei  = (const int*)d_in[1];
    const int*   et  = (const int*)d_in[2];
    const float* W1 = (const float*)d_in[3];
    const float* r1 = (const float*)d_in[4];
    const float* b1 = (const float*)d_in[5];
    const float* W2 = (const float*)d_in[6];
    const float* r2 = (const float*)d_in[7];
    const float* b2 = (const float*)d_in[8];
    const float* W3 = (const float*)d_in[9];
    const float* r3 = (const float*)d_in[10];
    const float* b3 = (const float*)d_in[11];
    float* out = (float*)d_out;

    cudaFuncSetAttribute(gemm_imma_kernel,
                         cudaFuncAttributeMaxDynamicSharedMemorySize, SMEM_TOTAL);

    zero_kernel<<<(N_NODES * NREL + 255) / 256, 256>>>();
    count_kernel<<<(N_EDGES + 255) / 256, 256>>>(ei, et);
    scan2_kernel<<<1, 1024>>>();
    permute_kernel<<<(N_EDGES + 255) / 256, 256>>>(ei, et);
    convert_w_kernel<<<3 * DIM, 128>>>(W1, r1, W2, r2, W3, r3);
    maxabs_kernel<<<592, 256>>>(emb);

    int qblocks = (int)(((size_t)M_PAD * XD / 4 + 255) / 256);
    quantx_kernel<<<qblocks, 256>>>(emb, 0, 0);

    dim3 ggrid(MTILES, DIM / TN);
    // layer 1
    gather_kernel<<<N_NODES, 96>>>();
    gemm_imma_kernel<<<ggrid, 256, SMEM_TOTAL>>>(0, b1, out, 0);
    quantx_kernel<<<qblocks, 256>>>(nullptr, 1, 1);
    // layer 2
    gather_kernel<<<N_NODES, 96>>>();
    gemm_imma_kernel<<<ggrid, 256, SMEM_TOTAL>>>(1, b2, out, 0);
    quantx_kernel<<<qblocks, 256>>>(nullptr, 1, 2);
    // layer 3
    gather_kernel<<<N_NODES, 96>>>();
    gemm_imma_kernel<<<ggrid, 256, SMEM_TOTAL>>>(2, b3, out, 1);
}

// round 14
// speedup vs baseline: 3.0638x; 3.0638x over previous
#include <cuda_runtime.h>
#include <cuda_fp16.h>
#include <cstdint>

#define N_NODES 50000
#define M_PAD   50048            // 391 * 128
#define N_EDGES 200000
#define DIM     384
#define XD      384
#define AGD     768
#define LK      1152             // logical K: [x | agg0 | agg1]
#define NREL    2

#define TM 128
#define TN 128
#define KC 32
#define NCHUNK 36               // LK / KC
#define MTILES 391
#define PRB 80                  // padded row bytes (32 fp16 = 64B + 16B pad)

// per-stage smem layout (bytes): A-hi, A-lo, B (single-word W)
#define ST_AH 0
#define ST_AL (TM * PRB)                  // 10240
#define ST_B  (2 * TM * PRB)              // 20480
#define STAGE_BYTES (2 * TM * PRB + TN * PRB)   // 30720
#define SMEM_TOTAL (2 * STAGE_BYTES)            // 61440

// ---------------- device scratch ----------------
__device__ __align__(16) __half g_xh[2][(size_t)M_PAD * XD];   // x hi (fp16 split)
__device__ __align__(16) __half g_xl[2][(size_t)M_PAD * XD];   // x lo
__device__ __align__(16) __half g_aggh[(size_t)M_PAD * AGD];
__device__ __align__(16) __half g_aggl[(size_t)M_PAD * AGD];
__device__ __align__(16) __half g_wt[(size_t)3 * DIM * LK];    // W single fp16, [L][n][k]
__device__ int   g_cnt[N_NODES * NREL];
__device__ int   g_cur[N_NODES];
__device__ int   g_off[N_NODES + 1];
__device__ int   g_psrc[N_EDGES];         // src * XD
__device__ float g_pscale[N_EDGES];       // +s rel0, -s rel1

// ---------------- helpers ----------------
__device__ __forceinline__ uint32_t smem_u32(const void* p) {
    uint32_t a;
    asm("{ .reg .u64 t; cvta.to.shared.u64 t, %1; cvt.u32.u64 %0, t; }" : "=r"(a) : "l"(p));
    return a;
}
#define LDSM_X4(r, a)                                                                   \
    asm volatile("ldmatrix.sync.aligned.m8n8.x4.shared.b16 {%0,%1,%2,%3}, [%4];"        \
        : "=r"((r)[0]), "=r"((r)[1]), "=r"((r)[2]), "=r"((r)[3]) : "r"(a))
#define CP_ASYNC16(dst, src) \
    asm volatile("cp.async.cg.shared.global [%0], [%1], 16;" :: "r"(dst), "l"(src))
#define CP_COMMIT()  asm volatile("cp.async.commit_group;" ::: "memory")
#define CP_WAIT1()   asm volatile("cp.async.wait_group 1;" ::: "memory")
#define CP_WAIT0()   asm volatile("cp.async.wait_group 0;" ::: "memory")

__device__ __forceinline__ void mma16816(float* d, const uint32_t* a,
                                         uint32_t b0, uint32_t b1) {
    asm volatile("mma.sync.aligned.m16n8k16.row.col.f32.f16.f16.f32 "
        "{%0,%1,%2,%3}, {%4,%5,%6,%7}, {%8,%9}, {%0,%1,%2,%3};"
        : "+f"(d[0]), "+f"(d[1]), "+f"(d[2]), "+f"(d[3])
        : "r"(a[0]), "r"(a[1]), "r"(a[2]), "r"(a[3]), "r"(b0), "r"(b1));
}

__device__ __forceinline__ void store_split2(__half* ph, __half* pl, float x, float y) {
    __half hx = __float2half_rn(x), hy = __float2half_rn(y);
    __half lx = __float2half_rn(x - __half2float(hx));
    __half ly = __float2half_rn(y - __half2float(hy));
    __half2 H; H.x = hx; H.y = hy;
    __half2 L; L.x = lx; L.y = ly;
    *(__half2*)ph = H;
    *(__half2*)pl = L;
}

// ---------------- edge preprocessing ----------------
__global__ void zero_kernel() {
    int i = blockIdx.x * blockDim.x + threadIdx.x;
    if (i < N_NODES * NREL) g_cnt[i] = 0;
    if (i < N_NODES) g_cur[i] = 0;
}
__device__ __forceinline__ int clampi(int v, int hi) {
    v = v < 0 ? 0 : v;
    return v >= hi ? hi - 1 : v;
}
__global__ void count_kernel(const int* __restrict__ ei, const int* __restrict__ et) {
    int e = blockIdx.x * blockDim.x + threadIdx.x;
    if (e >= N_EDGES) return;
    atomicAdd(&g_cnt[clampi(ei[N_EDGES + e], N_NODES) * NREL + clampi(et[e], NREL)], 1);
}
__global__ void scan2_kernel() {
    __shared__ int wsum[32];
    __shared__ int s_carry;
    const int tid = threadIdx.x;
    const int lane = tid & 31, w = tid >> 5;
    if (tid == 0) s_carry = 0;
    __syncthreads();
    for (int base = 0; base < N_NODES; base += 1024) {
        int i = base + tid;
        int v = (i < N_NODES) ? (g_cnt[i * NREL] + g_cnt[i * NREL + 1]) : 0;
        int incl = v;
#pragma unroll
        for (int o = 1; o < 32; o <<= 1) {
            int n = __shfl_up_sync(0xFFFFFFFF, incl, o);
            if (lane >= o) incl += n;
        }
        if (lane == 31) wsum[w] = incl;
        __syncthreads();
        if (w == 0) {
            int s = wsum[lane];
#pragma unroll
            for (int o = 1; o < 32; o <<= 1) {
                int n = __shfl_up_sync(0xFFFFFFFF, s, o);
                if (lane >= o) s += n;
            }
            wsum[lane] = s;
        }
        __syncthreads();
        int blk_excl = incl - v + (w > 0 ? wsum[w - 1] : 0);
        if (i < N_NODES) g_off[i] = s_carry + blk_excl;
        __syncthreads();
        if (tid == 0) s_carry += wsum[31];
        __syncthreads();
    }
    if (tid == 0) g_off[N_NODES] = s_carry;
}
__global__ void permute_kernel(const int* __restrict__ ei, const int* __restrict__ et) {
    int e = blockIdx.x * blockDim.x + threadIdx.x;
    if (e >= N_EDGES) return;
    int src = clampi(ei[e], N_NODES);
    int dst = clampi(ei[N_EDGES + e], N_NODES);
    int r   = clampi(et[e], NREL);
    int slot = g_off[dst] + atomicAdd(&g_cur[dst], 1);
    g_psrc[slot] = src * XD;
    int c = g_cnt[dst * NREL + r];
    float s = 1.0f / (float)(c > 0 ? c : 1);
    g_pscale[slot] = (r == 0) ? s : -s;
}

// ---------------- input split (layer 1): emb -> x buffer 0 ----------------
__global__ void convert_x_kernel(const float* __restrict__ ext) {
    size_t i2 = ((size_t)blockIdx.x * blockDim.x + threadIdx.x) * 2;
    if (i2 >= (size_t)N_NODES * XD) return;
    float2 v = *(const float2*)(ext + i2);
    store_split2(&g_xh[0][i2], &g_xl[0][i2], v.x, v.y);
}

// ---------------- weight build: single fp16, [layer][n][kcat] ----------------
__global__ void convert_w_kernel(const float* __restrict__ W1, const float* __restrict__ r1,
                                 const float* __restrict__ W2, const float* __restrict__ r2,
                                 const float* __restrict__ W3, const float* __restrict__ r3) {
    size_t i = (size_t)blockIdx.x * blockDim.x + threadIdx.x;
    if (i >= (size_t)3 * DIM * LK) return;
    int L = (int)(i / (DIM * LK));
    int rem = (int)(i % (DIM * LK));
    int n = rem / LK, k = rem % LK;
    const float* root = (L == 0) ? r1 : (L == 1) ? r2 : r3;
    const float* Wr   = (L == 0) ? W1 : (L == 1) ? W2 : W3;
    float v;
    if (k < DIM) v = root[(size_t)k * DIM + n];
    else {
        int r = (k - DIM) / DIM, kk = (k - DIM) % DIM;
        v = Wr[(size_t)r * DIM * DIM + (size_t)kk * DIM + n];
    }
    g_wt[i] = __float2half_rn(v);
}

// ---------------- CSR gather: agg from x[xsel] -> g_agg (fp16 split in/out) ----------------
__global__ __launch_bounds__(96) void gather_kernel(int xsel)
{
    const int d = blockIdx.x;
    const int c = threadIdx.x * 4;
    const int beg = g_off[d], end = g_off[d + 1];
    const __half* xh = g_xh[xsel];
    const __half* xl = g_xl[xsel];

    float4 a0 = make_float4(0.f, 0.f, 0.f, 0.f);
    float4 a1 = make_float4(0.f, 0.f, 0.f, 0.f);
    for (int j = beg; j < end; j++) {
        float s = g_pscale[j];
        int off = g_psrc[j] + c;
        __half2 h01 = *(const __half2*)(xh + off);
        __half2 h23 = *(const __half2*)(xh + off + 2);
        __half2 l01 = *(const __half2*)(xl + off);
        __half2 l23 = *(const __half2*)(xl + off + 2);
        float2 fh01 = __half22float2(h01), fh23 = __half22float2(h23);
        float2 fl01 = __half22float2(l01), fl23 = __half22float2(l23);
        float vx = fh01.x + fl01.x, vy = fh01.y + fl01.y;
        float vz = fh23.x + fl23.x, vw = fh23.y + fl23.y;
        if (s > 0.f) {
            a0.x += s * vx; a0.y += s * vy; a0.z += s * vz; a0.w += s * vw;
        } else {
            a1.x -= s * vx; a1.y -= s * vy; a1.z -= s * vz; a1.w -= s * vw;
        }
    }

    const size_t base = (size_t)d * AGD;
    store_split2(g_aggh + base + c,          g_aggl + base + c,          a0.x, a0.y);
    store_split2(g_aggh + base + c + 2,      g_aggl + base + c + 2,      a0.z, a0.w);
    store_split2(g_aggh + base + XD + c,     g_aggl + base + XD + c,     a1.x, a1.y);
    store_split2(g_aggh + base + XD + c + 2, g_aggl + base + XD + c + 2, a1.z, a1.w);
}

// ---------------- pipelined fp16x2 GEMM over logical K=1152, grid (MTILES, 3) ----------------
__device__ __forceinline__ void issue_chunk(
    uint32_t sb, int xsel, const __half* __restrict__ wt,
    int row0, int n0, int k0, int tid)
{
    const bool in_x = (k0 < XD);
    const __half* ah = in_x ? g_xh[xsel] : g_aggh;
    const __half* al = in_x ? g_xl[xsel] : g_aggl;
    const int astride = in_x ? XD : AGD;
    const int ak0 = in_x ? k0 : k0 - XD;
    // 3 buffers x 128 rows x 4 uint4 = 1536 transfers over 256 threads = 6 iters
#pragma unroll
    for (int i = 0; i < 6; i++) {
        int u = tid + i * 256;
        int buf = u >> 9;            // 0: Ah, 1: Al, 2: B
        int rem = u & 511;
        int row = rem >> 2;
        int c8  = (rem & 3) * 8;
        const __half* src;
        if (buf == 0)      src = ah + (size_t)(row0 + row) * astride + ak0 + c8;
        else if (buf == 1) src = al + (size_t)(row0 + row) * astride + ak0 + c8;
        else               src = wt + (size_t)(n0 + row) * LK + k0 + c8;
        uint32_t dst = sb + buf * 10240 + row * PRB + c8 * 2;
        CP_ASYNC16(dst, src);
    }
    CP_COMMIT();
}

__global__ __launch_bounds__(256, 2) void gemm_mma_kernel(
    int layer, int xsel, const float* __restrict__ bias,
    float* __restrict__ dout, int last)
{
    extern __shared__ char smem[];
    const uint32_t sbase = smem_u32(smem);
    const int tid = threadIdx.x;
    const int wid = tid >> 5, lane = tid & 31;
    const int row0 = blockIdx.x * TM;
    const int n0 = blockIdx.y * TN;

    const __half* wt = g_wt + (size_t)layer * DIM * LK;

    const int wr = (wid >> 1) * 32;
    const int wc = (wid & 1) * 64;
    const int lrow = lane & 15;
    const int lcol8 = (lane >> 4) * 8;

    float acc[64];
#pragma unroll
    for (int i = 0; i < 64; i++) acc[i] = 0.0f;

    issue_chunk(sbase, xsel, wt, row0, n0, 0, tid);

    for (int c = 0; c < NCHUNK; c++) {
        if (c + 1 < NCHUNK) {
            issue_chunk(sbase + ((c + 1) & 1) * STAGE_BYTES, xsel, wt,
                        row0, n0, (c + 1) * KC, tid);
            CP_WAIT1();
        } else {
            CP_WAIT0();
        }
        __syncthreads();

        const uint32_t stg = sbase + (c & 1) * STAGE_BYTES;
#pragma unroll
        for (int ks = 0; ks < 2; ks++) {
            const int kb = (ks * 16 + lcol8) * 2;
            uint32_t ah[2][4], al[2][4], b4[4][4];
#pragma unroll
            for (int mt = 0; mt < 2; mt++) {
                const uint32_t ra = (wr + mt * 16 + lrow) * PRB + kb;
                LDSM_X4(ah[mt], stg + ST_AH + ra);
                LDSM_X4(al[mt], stg + ST_AL + ra);
            }
#pragma unroll
            for (int g = 0; g < 4; g++)
                LDSM_X4(b4[g], stg + ST_B + (wc + g * 16 + lrow) * PRB + kb);
            // 2 passes against cached fragments: Ah*W, Al*W
#pragma unroll
            for (int mt = 0; mt < 2; mt++)
#pragma unroll
                for (int g = 0; g < 4; g++) {
                    float* d0 = &acc[((mt * 4 + g) * 2 + 0) * 4];
                    float* d1 = &acc[((mt * 4 + g) * 2 + 1) * 4];
                    mma16816(d0, ah[mt], b4[g][0], b4[g][2]);
                    mma16816(d1, ah[mt], b4[g][1], b4[g][3]);
                    mma16816(d0, al[mt], b4[g][0], b4[g][2]);
                    mma16816(d1, al[mt], b4[g][1], b4[g][3]);
                }
        }
        __syncthreads();
    }

    // ---- epilogue: +bias; non-last: relu + fp16 split into x[xsel^1]; last: fp32 dout ----
    const int qr = lane >> 2, qc = (lane & 3) * 2;
    __half* oxh = g_xh[xsel ^ 1];
    __half* oxl = g_xl[xsel ^ 1];
#pragma unroll
    for (int mt = 0; mt < 2; mt++) {
#pragma unroll
        for (int nt = 0; nt < 8; nt++) {
            const float* d = &acc[((mt * 4 + (nt >> 1)) * 2 + (nt & 1)) * 4];
            int m0 = row0 + wr + mt * 16 + qr;
            int n = n0 + wc + (nt >> 1) * 16 + (nt & 1) * 8 + qc;
            float2 bb = *(const float2*)(bias + n);
#pragma unroll
            for (int h = 0; h < 2; h++) {
                int m = m0 + h * 8;
                if (m >= N_NODES) continue;
                float x = d[h * 2 + 0] + bb.x;
                float y = d[h * 2 + 1] + bb.y;
                if (last) {
                    *(float2*)(dout + (size_t)m * DIM + n) = make_float2(x, y);
                } else {
                    x = fmaxf(x, 0.f);
                    y = fmaxf(y, 0.f);
                    size_t o = (size_t)m * XD + n;
                    store_split2(oxh + o, oxl + o, x, y);
                }
            }
        }
    }
}

// ---------------- launch ----------------
extern "C" void kernel_launch(void* const* d_in, const int* in_sizes, int n_in,
                              void* d_out, int out_size)
{
    const float* emb = (const float*)d_in[0];
    const int*   ei  = (const int*)d_in[1];
    const int*   et  = (const int*)d_in[2];
    const float* W1 = (const float*)d_in[3];
    const float* r1 = (const float*)d_in[4];
    const float* b1 = (const float*)d_in[5];
    const float* W2 = (const float*)d_in[6];
    const float* r2 = (const float*)d_in[7];
    const float* b2 = (const float*)d_in[8];
    const float* W3 = (const float*)d_in[9];
    const float* r3 = (const float*)d_in[10];
    const float* b3 = (const float*)d_in[11];
    float* out = (float*)d_out;

    cudaFuncSetAttribute(gemm_mma_kernel,
                         cudaFuncAttributeMaxDynamicSharedMemorySize, SMEM_TOTAL);

    zero_kernel<<<(N_NODES * NREL + 255) / 256, 256>>>();
    count_kernel<<<(N_EDGES + 255) / 256, 256>>>(ei, et);
    scan2_kernel<<<1, 1024>>>();
    permute_kernel<<<(N_EDGES + 255) / 256, 256>>>(ei, et);
    convert_w_kernel<<<(int)(((size_t)3 * DIM * LK + 255) / 256), 256>>>(W1, r1, W2, r2, W3, r3);

    dim3 ggrid(MTILES, 3);
    int cv_blocks = (int)(((size_t)N_NODES * XD / 2 + 255) / 256);

    convert_x_kernel<<<cv_blocks, 256>>>(emb);
    // layer 1: x[0] -> x[1]
    gather_kernel<<<N_NODES, 96>>>(0);
    gemm_mma_kernel<<<ggrid, 256, SMEM_TOTAL>>>(0, 0, b1, out, 0);
    // layer 2: x[1] -> x[0]
    gather_kernel<<<N_NODES, 96>>>(1);
    gemm_mma_kernel<<<ggrid, 256, SMEM_TOTAL>>>(1, 1, b2, out, 0);
    // layer 3: x[0] -> dout
    gather_kernel<<<N_NODES, 96>>>(0);
    gemm_mma_kernel<<<ggrid, 256, SMEM_TOTAL>>>(2, 0, b3, out, 1);
}

// round 15
// speedup vs baseline: 5.0655x; 1.6533x over previous
#include <cuda_runtime.h>
#include <cuda_fp16.h>
#include <cstdint>

#define N_NODES 50000
#define M_PAD   50048            // 391 * 128
#define N_EDGES 200000
#define DIM     384
#define XD      384
#define AGD     768
#define LK      1152             // logical K: [x | agg0 | agg1]
#define NREL    2

#define TM 128
#define TN 128
#define KC 32
#define NCHUNK 36               // LK / KC
#define MTILES 391
#define PRB 80                  // padded row bytes (32 fp16 = 64B + 16B pad)

// per-stage smem layout (bytes): A, B
#define ST_A 0
#define ST_B (TM * PRB)                   // 10240
#define STAGE_BYTES (TM * PRB + TN * PRB) // 20480
#define SMEM_TOTAL (2 * STAGE_BYTES)      // 40960

// ---------------- device scratch ----------------
__device__ __align__(16) __half g_x[2][(size_t)M_PAD * XD];   // ping-pong x (fp16)
__device__ __align__(16) __half g_agg[(size_t)M_PAD * AGD];   // aggregates (fp16)
__device__ __align__(16) __half g_wt[(size_t)3 * DIM * LK];   // W fp16, [L][n][k]
__device__ int   g_cnt[N_NODES * NREL];
__device__ int   g_cur[N_NODES];
__device__ int   g_off[N_NODES + 1];
__device__ int   g_psrc[N_EDGES];         // src * XD
__device__ float g_pscale[N_EDGES];       // +s rel0, -s rel1

// ---------------- helpers ----------------
__device__ __forceinline__ uint32_t smem_u32(const void* p) {
    uint32_t a;
    asm("{ .reg .u64 t; cvta.to.shared.u64 t, %1; cvt.u32.u64 %0, t; }" : "=r"(a) : "l"(p));
    return a;
}
#define LDSM_X4(r, a)                                                                   \
    asm volatile("ldmatrix.sync.aligned.m8n8.x4.shared.b16 {%0,%1,%2,%3}, [%4];"        \
        : "=r"((r)[0]), "=r"((r)[1]), "=r"((r)[2]), "=r"((r)[3]) : "r"(a))
#define CP_ASYNC16(dst, src) \
    asm volatile("cp.async.cg.shared.global [%0], [%1], 16;" :: "r"(dst), "l"(src))
#define CP_COMMIT()  asm volatile("cp.async.commit_group;" ::: "memory")
#define CP_WAIT1()   asm volatile("cp.async.wait_group 1;" ::: "memory")
#define CP_WAIT0()   asm volatile("cp.async.wait_group 0;" ::: "memory")

__device__ __forceinline__ void mma16816(float* d, const uint32_t* a,
                                         uint32_t b0, uint32_t b1) {
    asm volatile("mma.sync.aligned.m16n8k16.row.col.f32.f16.f16.f32 "
        "{%0,%1,%2,%3}, {%4,%5,%6,%7}, {%8,%9}, {%0,%1,%2,%3};"
        : "+f"(d[0]), "+f"(d[1]), "+f"(d[2]), "+f"(d[3])
        : "r"(a[0]), "r"(a[1]), "r"(a[2]), "r"(a[3]), "r"(b0), "r"(b1));
}

// ---------------- edge preprocessing ----------------
__global__ void zero_kernel() {
    int i = blockIdx.x * blockDim.x + threadIdx.x;
    if (i < N_NODES * NREL) g_cnt[i] = 0;
    if (i < N_NODES) g_cur[i] = 0;
}
__device__ __forceinline__ int clampi(int v, int hi) {
    v = v < 0 ? 0 : v;
    return v >= hi ? hi - 1 : v;
}
__global__ void count_kernel(const int* __restrict__ ei, const int* __restrict__ et) {
    int e = blockIdx.x * blockDim.x + threadIdx.x;
    if (e >= N_EDGES) return;
    atomicAdd(&g_cnt[clampi(ei[N_EDGES + e], N_NODES) * NREL + clampi(et[e], NREL)], 1);
}
__global__ void scan2_kernel() {
    __shared__ int wsum[32];
    __shared__ int s_carry;
    const int tid = threadIdx.x;
    const int lane = tid & 31, w = tid >> 5;
    if (tid == 0) s_carry = 0;
    __syncthreads();
    for (int base = 0; base < N_NODES; base += 1024) {
        int i = base + tid;
        int v = (i < N_NODES) ? (g_cnt[i * NREL] + g_cnt[i * NREL + 1]) : 0;
        int incl = v;
#pragma unroll
        for (int o = 1; o < 32; o <<= 1) {
            int n = __shfl_up_sync(0xFFFFFFFF, incl, o);
            if (lane >= o) incl += n;
        }
        if (lane == 31) wsum[w] = incl;
        __syncthreads();
        if (w == 0) {
            int s = wsum[lane];
#pragma unroll
            for (int o = 1; o < 32; o <<= 1) {
                int n = __shfl_up_sync(0xFFFFFFFF, s, o);
                if (lane >= o) s += n;
            }
            wsum[lane] = s;
        }
        __syncthreads();
        int blk_excl = incl - v + (w > 0 ? wsum[w - 1] : 0);
        if (i < N_NODES) g_off[i] = s_carry + blk_excl;
        __syncthreads();
        if (tid == 0) s_carry += wsum[31];
        __syncthreads();
    }
    if (tid == 0) g_off[N_NODES] = s_carry;
}
__global__ void permute_kernel(const int* __restrict__ ei, const int* __restrict__ et) {
    int e = blockIdx.x * blockDim.x + threadIdx.x;
    if (e >= N_EDGES) return;
    int src = clampi(ei[e], N_NODES);
    int dst = clampi(ei[N_EDGES + e], N_NODES);
    int r   = clampi(et[e], NREL);
    int slot = g_off[dst] + atomicAdd(&g_cur[dst], 1);
    g_psrc[slot] = src * XD;
    int c = g_cnt[dst * NREL + r];
    float s = 1.0f / (float)(c > 0 ? c : 1);
    g_pscale[slot] = (r == 0) ? s : -s;
}

// ---------------- input convert (layer 1): emb -> x buffer 0 ----------------
__global__ void convert_x_kernel(const float* __restrict__ ext) {
    size_t i2 = ((size_t)blockIdx.x * blockDim.x + threadIdx.x) * 2;
    if (i2 >= (size_t)N_NODES * XD) return;
    float2 v = *(const float2*)(ext + i2);
    __half2 h;
    h.x = __float2half_rn(v.x);
    h.y = __float2half_rn(v.y);
    *(__half2*)&g_x[0][i2] = h;
}

// ---------------- weight build: fp16, [layer][n][kcat] ----------------
__global__ void convert_w_kernel(const float* __restrict__ W1, const float* __restrict__ r1,
                                 const float* __restrict__ W2, const float* __restrict__ r2,
                                 const float* __restrict__ W3, const float* __restrict__ r3) {
    size_t i = (size_t)blockIdx.x * blockDim.x + threadIdx.x;
    if (i >= (size_t)3 * DIM * LK) return;
    int L = (int)(i / (DIM * LK));
    int rem = (int)(i % (DIM * LK));
    int n = rem / LK, k = rem % LK;
    const float* root = (L == 0) ? r1 : (L == 1) ? r2 : r3;
    const float* Wr   = (L == 0) ? W1 : (L == 1) ? W2 : W3;
    float v;
    if (k < DIM) v = root[(size_t)k * DIM + n];
    else {
        int r = (k - DIM) / DIM, kk = (k - DIM) % DIM;
        v = Wr[(size_t)r * DIM * DIM + (size_t)kk * DIM + n];
    }
    g_wt[i] = __float2half_rn(v);
}

// ---------------- CSR gather: agg from x[xsel] -> g_agg (fp16 in/out, fp32 accum) ----------------
__global__ __launch_bounds__(96) void gather_kernel(int xsel)
{
    const int d = blockIdx.x;
    const int c = threadIdx.x * 4;
    const int beg = g_off[d], end = g_off[d + 1];
    const __half* x = g_x[xsel];

    float4 a0 = make_float4(0.f, 0.f, 0.f, 0.f);
    float4 a1 = make_float4(0.f, 0.f, 0.f, 0.f);
    for (int j = beg; j < end; j++) {
        float s = g_pscale[j];
        int off = g_psrc[j] + c;
        __half2 h01 = *(const __half2*)(x + off);
        __half2 h23 = *(const __half2*)(x + off + 2);
        float2 f01 = __half22float2(h01), f23 = __half22float2(h23);
        if (s > 0.f) {
            a0.x += s * f01.x; a0.y += s * f01.y; a0.z += s * f23.x; a0.w += s * f23.y;
        } else {
            a1.x -= s * f01.x; a1.y -= s * f01.y; a1.z -= s * f23.x; a1.w -= s * f23.y;
        }
    }

    const size_t base = (size_t)d * AGD;
    __half2 o;
    o.x = __float2half_rn(a0.x); o.y = __float2half_rn(a0.y);
    *(__half2*)(g_agg + base + c) = o;
    o.x = __float2half_rn(a0.z); o.y = __float2half_rn(a0.w);
    *(__half2*)(g_agg + base + c + 2) = o;
    o.x = __float2half_rn(a1.x); o.y = __float2half_rn(a1.y);
    *(__half2*)(g_agg + base + XD + c) = o;
    o.x = __float2half_rn(a1.z); o.y = __float2half_rn(a1.w);
    *(__half2*)(g_agg + base + XD + c + 2) = o;
}

// ---------------- pipelined fp16 GEMM over logical K=1152, grid (MTILES, 3) ----------------
__device__ __forceinline__ void issue_chunk(
    uint32_t sb, int xsel, const __half* __restrict__ wt,
    int row0, int n0, int k0, int tid)
{
    const bool in_x = (k0 < XD);
    const __half* a = in_x ? g_x[xsel] : g_agg;
    const int astride = in_x ? XD : AGD;
    const int ak0 = in_x ? k0 : k0 - XD;
    // 2 buffers x 128 rows x 4 uint4 = 1024 transfers over 256 threads = 4 iters
#pragma unroll
    for (int i = 0; i < 4; i++) {
        int u = tid + i * 256;
        int buf = u >> 9;            // 0: A, 1: B
        int rem = u & 511;
        int row = rem >> 2;
        int c8  = (rem & 3) * 8;
        const __half* src = buf
            ? wt + (size_t)(n0 + row) * LK + k0 + c8
            : a + (size_t)(row0 + row) * astride + ak0 + c8;
        uint32_t dst = sb + buf * 10240 + row * PRB + c8 * 2;
        CP_ASYNC16(dst, src);
    }
    CP_COMMIT();
}

__global__ __launch_bounds__(256, 2) void gemm_mma_kernel(
    int layer, int xsel, const float* __restrict__ bias,
    float* __restrict__ dout, int last)
{
    extern __shared__ char smem[];
    const uint32_t sbase = smem_u32(smem);
    const int tid = threadIdx.x;
    const int wid = tid >> 5, lane = tid & 31;
    const int row0 = blockIdx.x * TM;
    const int n0 = blockIdx.y * TN;

    const __half* wt = g_wt + (size_t)layer * DIM * LK;

    const int wr = (wid >> 1) * 32;
    const int wc = (wid & 1) * 64;
    const int lrow = lane & 15;
    const int lcol8 = (lane >> 4) * 8;

    float acc[64];
#pragma unroll
    for (int i = 0; i < 64; i++) acc[i] = 0.0f;

    issue_chunk(sbase, xsel, wt, row0, n0, 0, tid);

    for (int c = 0; c < NCHUNK; c++) {
        if (c + 1 < NCHUNK) {
            issue_chunk(sbase + ((c + 1) & 1) * STAGE_BYTES, xsel, wt,
                        row0, n0, (c + 1) * KC, tid);
            CP_WAIT1();
        } else {
            CP_WAIT0();
        }
        __syncthreads();

        const uint32_t stg = sbase + (c & 1) * STAGE_BYTES;
#pragma unroll
        for (int ks = 0; ks < 2; ks++) {
            const int kb = (ks * 16 + lcol8) * 2;
            uint32_t a2[2][4], b4[4][4];
#pragma unroll
            for (int mt = 0; mt < 2; mt++)
                LDSM_X4(a2[mt], stg + ST_A + (wr + mt * 16 + lrow) * PRB + kb);
#pragma unroll
            for (int g = 0; g < 4; g++)
                LDSM_X4(b4[g], stg + ST_B + (wc + g * 16 + lrow) * PRB + kb);
#pragma unroll
            for (int mt = 0; mt < 2; mt++)
#pragma unroll
                for (int g = 0; g < 4; g++) {
                    float* d0 = &acc[((mt * 4 + g) * 2 + 0) * 4];
                    float* d1 = &acc[((mt * 4 + g) * 2 + 1) * 4];
                    mma16816(d0, a2[mt], b4[g][0], b4[g][2]);
                    mma16816(d1, a2[mt], b4[g][1], b4[g][3]);
                }
        }
        __syncthreads();
    }

    // ---- epilogue: +bias; non-last: relu + fp16 into x[xsel^1]; last: fp32 dout ----
    const int qr = lane >> 2, qc = (lane & 3) * 2;
    __half* ox = g_x[xsel ^ 1];
#pragma unroll
    for (int mt = 0; mt < 2; mt++) {
#pragma unroll
        for (int nt = 0; nt < 8; nt++) {
            const float* d = &acc[((mt * 4 + (nt >> 1)) * 2 + (nt & 1)) * 4];
            int m0 = row0 + wr + mt * 16 + qr;
            int n = n0 + wc + (nt >> 1) * 16 + (nt & 1) * 8 + qc;
            float2 bb = *(const float2*)(bias + n);
#pragma unroll
            for (int h = 0; h < 2; h++) {
                int m = m0 + h * 8;
                if (m >= N_NODES) continue;
                float x = d[h * 2 + 0] + bb.x;
                float y = d[h * 2 + 1] + bb.y;
                if (last) {
                    *(float2*)(dout + (size_t)m * DIM + n) = make_float2(x, y);
                } else {
                    __half2 o;
                    o.x = __float2half_rn(fmaxf(x, 0.f));
                    o.y = __float2half_rn(fmaxf(y, 0.f));
                    *(__half2*)(ox + (size_t)m * XD + n) = o;
                }
            }
        }
    }
}

// ---------------- launch ----------------
extern "C" void kernel_launch(void* const* d_in, const int* in_sizes, int n_in,
                              void* d_out, int out_size)
{
    const float* emb = (const float*)d_in[0];
    const int*   ei  = (const int*)d_in[1];
    const int*   et  = (const int*)d_in[2];
    const float* W1 = (const float*)d_in[3];
    const float* r1 = (const float*)d_in[4];
    const float* b1 = (const float*)d_in[5];
    const float* W2 = (const float*)d_in[6];
    const float* r2 = (const float*)d_in[7];
    const float* b2 = (const float*)d_in[8];
    const float* W3 = (const float*)d_in[9];
    const float* r3 = (const float*)d_in[10];
    const float* b3 = (const float*)d_in[11];
    float* out = (float*)d_out;

    cudaFuncSetAttribute(gemm_mma_kernel,
                         cudaFuncAttributeMaxDynamicSharedMemorySize, SMEM_TOTAL);

    zero_kernel<<<(N_NODES * NREL + 255) / 256, 256>>>();
    count_kernel<<<(N_EDGES + 255) / 256, 256>>>(ei, et);
    scan2_kernel<<<1, 1024>>>();
    permute_kernel<<<(N_EDGES + 255) / 256, 256>>>(ei, et);
    convert_w_kernel<<<(int)(((size_t)3 * DIM * LK + 255) / 256), 256>>>(W1, r1, W2, r2, W3, r3);

    dim3 ggrid(MTILES, 3);
    int cv_blocks = (int)(((size_t)N_NODES * XD / 2 + 255) / 256);

    convert_x_kernel<<<cv_blocks, 256>>>(emb);
    // layer 1: x[0] -> x[1]
    gather_kernel<<<N_NODES, 96>>>(0);
    gemm_mma_kernel<<<ggrid, 256, SMEM_TOTAL>>>(0, 0, b1, out, 0);
    // layer 2: x[1] -> x[0]
    gather_kernel<<<N_NODES, 96>>>(1);
    gemm_mma_kernel<<<ggrid, 256, SMEM_TOTAL>>>(1, 1, b2, out, 0);
    // layer 3: x[0] -> dout
    gather_kernel<<<N_NODES, 96>>>(0);
    gemm_mma_kernel<<<ggrid, 256, SMEM_TOTAL>>>(2, 0, b3, out, 1);
}

// round 16
// speedup vs baseline: 5.6175x; 1.1090x over previous
#include <cuda_runtime.h>
#include <cuda_fp16.h>
#include <cstdint>

#define N_NODES 50000
#define M_PAD   50048            // 391 * 128
#define N_EDGES 200000
#define DIM     384
#define XD      384
#define AGD     768
#define LK      1152             // logical K: [x | agg0 | agg1]
#define NREL    2
#define NB      49               // scan blocks: ceil(50000/1024)

#define TM 128
#define TN 128
#define KC 64
#define NCHUNK 18               // LK / KC
#define MTILES 391
#define PRB 144                 // padded row bytes (64 fp16 = 128B + 16B pad)

// per-stage smem layout (bytes): A, B
#define ST_A 0
#define ST_B (TM * PRB)                   // 18432
#define STAGE_BYTES (TM * PRB + TN * PRB) // 36864
#define SMEM_TOTAL (2 * STAGE_BYTES)      // 73728

// ---------------- device scratch ----------------
__device__ __align__(16) __half g_x[2][(size_t)M_PAD * XD];   // ping-pong x (fp16)
__device__ __align__(16) __half g_agg[(size_t)M_PAD * AGD];   // aggregates (fp16)
__device__ __align__(16) __half g_wt[(size_t)3 * DIM * LK];   // W fp16, [L][n][k]
__device__ int   g_cnt[N_NODES * NREL];
__device__ int   g_cur[N_NODES];
__device__ int   g_off[N_NODES + 1];
__device__ int   g_bsum[NB];
__device__ int   g_psrc[N_EDGES];         // src * XD
__device__ float g_pscale[N_EDGES];       // +s rel0, -s rel1

// ---------------- helpers ----------------
__device__ __forceinline__ uint32_t smem_u32(const void* p) {
    uint32_t a;
    asm("{ .reg .u64 t; cvta.to.shared.u64 t, %1; cvt.u32.u64 %0, t; }" : "=r"(a) : "l"(p));
    return a;
}
#define LDSM_X4(r, a)                                                                   \
    asm volatile("ldmatrix.sync.aligned.m8n8.x4.shared.b16 {%0,%1,%2,%3}, [%4];"        \
        : "=r"((r)[0]), "=r"((r)[1]), "=r"((r)[2]), "=r"((r)[3]) : "r"(a))
#define CP_ASYNC16(dst, src) \
    asm volatile("cp.async.cg.shared.global [%0], [%1], 16;" :: "r"(dst), "l"(src))
#define CP_COMMIT()  asm volatile("cp.async.commit_group;" ::: "memory")
#define CP_WAIT1()   asm volatile("cp.async.wait_group 1;" ::: "memory")
#define CP_WAIT0()   asm volatile("cp.async.wait_group 0;" ::: "memory")

__device__ __forceinline__ void mma16816(float* d, const uint32_t* a,
                                         uint32_t b0, uint32_t b1) {
    asm volatile("mma.sync.aligned.m16n8k16.row.col.f32.f16.f16.f32 "
        "{%0,%1,%2,%3}, {%4,%5,%6,%7}, {%8,%9}, {%0,%1,%2,%3};"
        : "+f"(d[0]), "+f"(d[1]), "+f"(d[2]), "+f"(d[3])
        : "r"(a[0]), "r"(a[1]), "r"(a[2]), "r"(a[3]), "r"(b0), "r"(b1));
}

// ---------------- edge preprocessing ----------------
__global__ void zero_kernel() {
    int i = blockIdx.x * blockDim.x + threadIdx.x;
    if (i < N_NODES * NREL) g_cnt[i] = 0;
    if (i < N_NODES) g_cur[i] = 0;
}
__device__ __forceinline__ int clampi(int v, int hi) {
    v = v < 0 ? 0 : v;
    return v >= hi ? hi - 1 : v;
}
__global__ void count_kernel(const int* __restrict__ ei, const int* __restrict__ et) {
    int e = blockIdx.x * blockDim.x + threadIdx.x;
    if (e >= N_EDGES) return;
    atomicAdd(&g_cnt[clampi(ei[N_EDGES + e], N_NODES) * NREL + clampi(et[e], NREL)], 1);
}

// ---- 3-phase parallel exclusive scan of per-dst total degree -> g_off ----
__global__ void scan_a_kernel() {
    __shared__ int wsum[32];
    const int tid = threadIdx.x;
    const int lane = tid & 31, w = tid >> 5;
    int i = blockIdx.x * 1024 + tid;
    int v = (i < N_NODES) ? (g_cnt[i * NREL] + g_cnt[i * NREL + 1]) : 0;
    int incl = v;
#pragma unroll
    for (int o = 1; o < 32; o <<= 1) {
        int n = __shfl_up_sync(0xFFFFFFFF, incl, o);
        if (lane >= o) incl += n;
    }
    if (lane == 31) wsum[w] = incl;
    __syncthreads();
    if (w == 0) {
        int s = wsum[lane];
#pragma unroll
        for (int o = 1; o < 32; o <<= 1) {
            int n = __shfl_up_sync(0xFFFFFFFF, s, o);
            if (lane >= o) s += n;
        }
        wsum[lane] = s;
    }
    __syncthreads();
    int excl = incl - v + (w > 0 ? wsum[w - 1] : 0);
    if (i < N_NODES) g_off[i] = excl;
    if (tid == 1023) g_bsum[blockIdx.x] = wsum[31];
}
__global__ void scan_b_kernel() {
    if (threadIdx.x == 0) {
        int acc = 0;
        for (int b = 0; b < NB; b++) {
            int v = g_bsum[b];
            g_bsum[b] = acc;
            acc += v;
        }
        g_off[N_NODES] = acc;
    }
}
__global__ void scan_c_kernel() {
    int i = blockIdx.x * 1024 + threadIdx.x;
    if (i < N_NODES) g_off[i] += g_bsum[blockIdx.x];
}

__global__ void permute_kernel(const int* __restrict__ ei, const int* __restrict__ et) {
    int e = blockIdx.x * blockDim.x + threadIdx.x;
    if (e >= N_EDGES) return;
    int src = clampi(ei[e], N_NODES);
    int dst = clampi(ei[N_EDGES + e], N_NODES);
    int r   = clampi(et[e], NREL);
    int slot = g_off[dst] + atomicAdd(&g_cur[dst], 1);
    g_psrc[slot] = src * XD;
    int c = g_cnt[dst * NREL + r];
    float s = 1.0f / (float)(c > 0 ? c : 1);
    g_pscale[slot] = (r == 0) ? s : -s;
}

// ---------------- input convert (layer 1): emb -> x buffer 0 ----------------
__global__ void convert_x_kernel(const float* __restrict__ ext) {
    size_t i2 = ((size_t)blockIdx.x * blockDim.x + threadIdx.x) * 2;
    if (i2 >= (size_t)N_NODES * XD) return;
    float2 v = *(const float2*)(ext + i2);
    __half2 h;
    h.x = __float2half_rn(v.x);
    h.y = __float2half_rn(v.y);
    *(__half2*)&g_x[0][i2] = h;
}

// ---------------- weight build: fp16, [layer][n][kcat] ----------------
__global__ void convert_w_kernel(const float* __restrict__ W1, const float* __restrict__ r1,
                                 const float* __restrict__ W2, const float* __restrict__ r2,
                                 const float* __restrict__ W3, const float* __restrict__ r3) {
    size_t i = (size_t)blockIdx.x * blockDim.x + threadIdx.x;
    if (i >= (size_t)3 * DIM * LK) return;
    int L = (int)(i / (DIM * LK));
    int rem = (int)(i % (DIM * LK));
    int n = rem / LK, k = rem % LK;
    const float* root = (L == 0) ? r1 : (L == 1) ? r2 : r3;
    const float* Wr   = (L == 0) ? W1 : (L == 1) ? W2 : W3;
    float v;
    if (k < DIM) v = root[(size_t)k * DIM + n];
    else {
        int r = (k - DIM) / DIM, kk = (k - DIM) % DIM;
        v = Wr[(size_t)r * DIM * DIM + (size_t)kk * DIM + n];
    }
    g_wt[i] = __float2half_rn(v);
}

// ---------------- CSR gather (2-edge ILP): agg from x[xsel] -> g_agg ----------------
__global__ __launch_bounds__(96) void gather_kernel(int xsel)
{
    const int d = blockIdx.x;
    const int c = threadIdx.x * 4;
    const int beg = g_off[d], end = g_off[d + 1];
    const __half* x = g_x[xsel];

    float4 a0 = make_float4(0.f, 0.f, 0.f, 0.f);
    float4 a1 = make_float4(0.f, 0.f, 0.f, 0.f);
    int j = beg;
    for (; j + 1 < end; j += 2) {
        float s0 = g_pscale[j], s1 = g_pscale[j + 1];
        int o0 = g_psrc[j] + c, o1 = g_psrc[j + 1] + c;
        __half2 pa0 = *(const __half2*)(x + o0);
        __half2 pa1 = *(const __half2*)(x + o0 + 2);
        __half2 pb0 = *(const __half2*)(x + o1);
        __half2 pb1 = *(const __half2*)(x + o1 + 2);
        float2 fa0 = __half22float2(pa0), fa1 = __half22float2(pa1);
        float2 fb0 = __half22float2(pb0), fb1 = __half22float2(pb1);
        if (s0 > 0.f) {
            a0.x += s0 * fa0.x; a0.y += s0 * fa0.y; a0.z += s0 * fa1.x; a0.w += s0 * fa1.y;
        } else {
            a1.x -= s0 * fa0.x; a1.y -= s0 * fa0.y; a1.z -= s0 * fa1.x; a1.w -= s0 * fa1.y;
        }
        if (s1 > 0.f) {
            a0.x += s1 * fb0.x; a0.y += s1 * fb0.y; a0.z += s1 * fb1.x; a0.w += s1 * fb1.y;
        } else {
            a1.x -= s1 * fb0.x; a1.y -= s1 * fb0.y; a1.z -= s1 * fb1.x; a1.w -= s1 * fb1.y;
        }
    }
    if (j < end) {
        float s = g_pscale[j];
        int off = g_psrc[j] + c;
        __half2 h01 = *(const __half2*)(x + off);
        __half2 h23 = *(const __half2*)(x + off + 2);
        float2 f01 = __half22float2(h01), f23 = __half22float2(h23);
        if (s > 0.f) {
            a0.x += s * f01.x; a0.y += s * f01.y; a0.z += s * f23.x; a0.w += s * f23.y;
        } else {
            a1.x -= s * f01.x; a1.y -= s * f01.y; a1.z -= s * f23.x; a1.w -= s * f23.y;
        }
    }

    const size_t base = (size_t)d * AGD;
    __half2 o;
    o.x = __float2half_rn(a0.x); o.y = __float2half_rn(a0.y);
    *(__half2*)(g_agg + base + c) = o;
    o.x = __float2half_rn(a0.z); o.y = __float2half_rn(a0.w);
    *(__half2*)(g_agg + base + c + 2) = o;
    o.x = __float2half_rn(a1.x); o.y = __float2half_rn(a1.y);
    *(__half2*)(g_agg + base + XD + c) = o;
    o.x = __float2half_rn(a1.z); o.y = __float2half_rn(a1.w);
    *(__half2*)(g_agg + base + XD + c + 2) = o;
}

// ---------------- pipelined fp16 GEMM over logical K=1152, grid (MTILES, 3) ----------------
__device__ __forceinline__ void issue_chunk(
    uint32_t sb, int xsel, const __half* __restrict__ wt,
    int row0, int n0, int k0, int tid)
{
    const bool in_x = (k0 < XD);
    const __half* a = in_x ? g_x[xsel] : g_agg;
    const int astride = in_x ? XD : AGD;
    const int ak0 = in_x ? k0 : k0 - XD;
    // 2 buffers x 128 rows x 8 uint4 = 2048 transfers over 256 threads = 8 iters
#pragma unroll
    for (int i = 0; i < 8; i++) {
        int u = tid + i * 256;
        int buf = u >> 10;           // 0: A, 1: B
        int rem = u & 1023;
        int row = rem >> 3;
        int c8  = (rem & 7) * 8;
        const __half* src = buf
            ? wt + (size_t)(n0 + row) * LK + k0 + c8
            : a + (size_t)(row0 + row) * astride + ak0 + c8;
        uint32_t dst = sb + buf * ST_B + row * PRB + c8 * 2;
        CP_ASYNC16(dst, src);
    }
    CP_COMMIT();
}

__global__ __launch_bounds__(256, 2) void gemm_mma_kernel(
    int layer, int xsel, const float* __restrict__ bias,
    float* __restrict__ dout, int last)
{
    extern __shared__ char smem[];
    const uint32_t sbase = smem_u32(smem);
    const int tid = threadIdx.x;
    const int wid = tid >> 5, lane = tid & 31;
    const int row0 = blockIdx.x * TM;
    const int n0 = blockIdx.y * TN;

    const __half* wt = g_wt + (size_t)layer * DIM * LK;

    const int wr = (wid >> 1) * 32;
    const int wc = (wid & 1) * 64;
    const int lrow = lane & 15;
    const int lcol8 = (lane >> 4) * 8;

    float acc[64];
#pragma unroll
    for (int i = 0; i < 64; i++) acc[i] = 0.0f;

    issue_chunk(sbase, xsel, wt, row0, n0, 0, tid);

    for (int c = 0; c < NCHUNK; c++) {
        if (c + 1 < NCHUNK) {
            issue_chunk(sbase + ((c + 1) & 1) * STAGE_BYTES, xsel, wt,
                        row0, n0, (c + 1) * KC, tid);
            CP_WAIT1();
        } else {
            CP_WAIT0();
        }
        __syncthreads();

        const uint32_t stg = sbase + (c & 1) * STAGE_BYTES;
#pragma unroll
        for (int ks = 0; ks < 4; ks++) {
            const int kb = (ks * 16 + lcol8) * 2;
            uint32_t a2[2][4], b4[4][4];
#pragma unroll
            for (int mt = 0; mt < 2; mt++)
                LDSM_X4(a2[mt], stg + ST_A + (wr + mt * 16 + lrow) * PRB + kb);
#pragma unroll
            for (int g = 0; g < 4; g++)
                LDSM_X4(b4[g], stg + ST_B + (wc + g * 16 + lrow) * PRB + kb);
#pragma unroll
            for (int mt = 0; mt < 2; mt++)
#pragma unroll
                for (int g = 0; g < 4; g++) {
                    float* d0 = &acc[((mt * 4 + g) * 2 + 0) * 4];
                    float* d1 = &acc[((mt * 4 + g) * 2 + 1) * 4];
                    mma16816(d0, a2[mt], b4[g][0], b4[g][2]);
                    mma16816(d1, a2[mt], b4[g][1], b4[g][3]);
                }
        }
        __syncthreads();
    }

    // ---- epilogue: +bias; non-last: relu + fp16 into x[xsel^1]; last: fp32 dout ----
    const int qr = lane >> 2, qc = (lane & 3) * 2;
    __half* ox = g_x[xsel ^ 1];
#pragma unroll
    for (int mt = 0; mt < 2; mt++) {
#pragma unroll
        for (int nt = 0; nt < 8; nt++) {
            const float* d = &acc[((mt * 4 + (nt >> 1)) * 2 + (nt & 1)) * 4];
            int m0 = row0 + wr + mt * 16 + qr;
            int n = n0 + wc + (nt >> 1) * 16 + (nt & 1) * 8 + qc;
            float2 bb = *(const float2*)(bias + n);
#pragma unroll
            for (int h = 0; h < 2; h++) {
                int m = m0 + h * 8;
                if (m >= N_NODES) continue;
                float x = d[h * 2 + 0] + bb.x;
                float y = d[h * 2 + 1] + bb.y;
                if (last) {
                    *(float2*)(dout + (size_t)m * DIM + n) = make_float2(x, y);
                } else {
                    __half2 o;
                    o.x = __float2half_rn(fmaxf(x, 0.f));
                    o.y = __float2half_rn(fmaxf(y, 0.f));
                    *(__half2*)(ox + (size_t)m * XD + n) = o;
                }
            }
        }
    }
}

// ---------------- launch ----------------
extern "C" void kernel_launch(void* const* d_in, const int* in_sizes, int n_in,
                              void* d_out, int out_size)
{
    const float* emb = (const float*)d_in[0];
    const int*   ei  = (const int*)d_in[1];
    const int*   et  = (const int*)d_in[2];
    const float* W1 = (const float*)d_in[3];
    const float* r1 = (const float*)d_in[4];
    const float* b1 = (const float*)d_in[5];
    const float* W2 = (const float*)d_in[6];
    const float* r2 = (const float*)d_in[7];
    const float* b2 = (const float*)d_in[8];
    const float* W3 = (const float*)d_in[9];
    const float* r3 = (const float*)d_in[10];
    const float* b3 = (const float*)d_in[11];
    float* out = (float*)d_out;

    cudaFuncSetAttribute(gemm_mma_kernel,
                         cudaFuncAttributeMaxDynamicSharedMemorySize, SMEM_TOTAL);

    zero_kernel<<<(N_NODES * NREL + 255) / 256, 256>>>();
    count_kernel<<<(N_EDGES + 255) / 256, 256>>>(ei, et);
    scan_a_kernel<<<NB, 1024>>>();
    scan_b_kernel<<<1, 32>>>();
    scan_c_kernel<<<NB, 1024>>>();
    permute_kernel<<<(N_EDGES + 255) / 256, 256>>>(ei, et);
    convert_w_kernel<<<(int)(((size_t)3 * DIM * LK + 255) / 256), 256>>>(W1, r1, W2, r2, W3, r3);

    dim3 ggrid(MTILES, 3);
    int cv_blocks = (int)(((size_t)N_NODES * XD / 2 + 255) / 256);

    convert_x_kernel<<<cv_blocks, 256>>>(emb);
    // layer 1: x[0] -> x[1]
    gather_kernel<<<N_NODES, 96>>>(0);
    gemm_mma_kernel<<<ggrid, 256, SMEM_TOTAL>>>(0, 0, b1, out, 0);
    // layer 2: x[1] -> x[0]
    gather_kernel<<<N_NODES, 96>>>(1);
    gemm_mma_kernel<<<ggrid, 256, SMEM_TOTAL>>>(1, 1, b2, out, 0);
    // layer 3: x[0] -> dout
    gather_kernel<<<N_NODES, 96>>>(0);
    gemm_mma_kernel<<<ggrid, 256, SMEM_TOTAL>>>(2, 0, b3, out, 1);
}

// round 17
// speedup vs baseline: 5.8070x; 1.0337x over previous
#include <cuda_runtime.h>
#include <cuda_fp16.h>
#include <cstdint>

#define N_NODES 50000
#define M_PAD   50048            // 391 * 128
#define N_EDGES 200000
#define DIM     384
#define XD      384
#define AGD     768
#define LK      1152             // logical K: [x | agg0 | agg1]
#define NREL    2
#define NB      49               // scan blocks: ceil(50000/1024)

#define TM 128
#define TN 128
#define KC 64
#define NCHUNK 18               // LK / KC
#define MTILES 391
#define PRB 144                 // padded row bytes (64 fp16 = 128B + 16B pad)

// per-stage smem layout (bytes): A, B
#define ST_A 0
#define ST_B (TM * PRB)                   // 18432
#define STAGE_BYTES (TM * PRB + TN * PRB) // 36864
#define SMEM_TOTAL (2 * STAGE_BYTES)      // 73728

// ---------------- device scratch ----------------
__device__ __align__(16) __half g_x[2][(size_t)M_PAD * XD];   // ping-pong x (fp16)
__device__ __align__(16) __half g_agg[(size_t)M_PAD * AGD];   // aggregates (fp16)
__device__ __align__(16) __half g_wt[(size_t)3 * DIM * LK];   // W fp16, [L][n][k]
__device__ int   g_cnt[N_NODES * NREL];
__device__ int   g_cur[N_NODES];
__device__ int   g_off[N_NODES + 1];
__device__ int   g_bsum[64];
__device__ int   g_psrc[N_EDGES];         // src * XD
__device__ float g_pscale[N_EDGES];       // +s rel0, -s rel1

// ---------------- helpers ----------------
__device__ __forceinline__ uint32_t smem_u32(const void* p) {
    uint32_t a;
    asm("{ .reg .u64 t; cvta.to.shared.u64 t, %1; cvt.u32.u64 %0, t; }" : "=r"(a) : "l"(p));
    return a;
}
#define LDSM_X4(r, a)                                                                   \
    asm volatile("ldmatrix.sync.aligned.m8n8.x4.shared.b16 {%0,%1,%2,%3}, [%4];"        \
        : "=r"((r)[0]), "=r"((r)[1]), "=r"((r)[2]), "=r"((r)[3]) : "r"(a))
#define CP_ASYNC16(dst, src) \
    asm volatile("cp.async.cg.shared.global [%0], [%1], 16;" :: "r"(dst), "l"(src))
#define CP_COMMIT()  asm volatile("cp.async.commit_group;" ::: "memory")
#define CP_WAIT1()   asm volatile("cp.async.wait_group 1;" ::: "memory")
#define CP_WAIT0()   asm volatile("cp.async.wait_group 0;" ::: "memory")

__device__ __forceinline__ void mma16816(float* d, const uint32_t* a,
                                         uint32_t b0, uint32_t b1) {
    asm volatile("mma.sync.aligned.m16n8k16.row.col.f32.f16.f16.f32 "
        "{%0,%1,%2,%3}, {%4,%5,%6,%7}, {%8,%9}, {%0,%1,%2,%3};"
        : "+f"(d[0]), "+f"(d[1]), "+f"(d[2]), "+f"(d[3])
        : "r"(a[0]), "r"(a[1]), "r"(a[2]), "r"(a[3]), "r"(b0), "r"(b1));
}

__device__ __forceinline__ void edge_acc(const __half* __restrict__ x, float s, int off,
                                         float4& a0, float4& a1) {
    __half2 h01 = *(const __half2*)(x + off);
    __half2 h23 = *(const __half2*)(x + off + 2);
    float2 f01 = __half22float2(h01), f23 = __half22float2(h23);
    if (s > 0.f) {
        a0.x += s * f01.x; a0.y += s * f01.y; a0.z += s * f23.x; a0.w += s * f23.y;
    } else {
        a1.x -= s * f01.x; a1.y -= s * f01.y; a1.z -= s * f23.x; a1.w -= s * f23.y;
    }
}

// ---------------- edge preprocessing ----------------
__global__ void zero_kernel() {
    int i = blockIdx.x * blockDim.x + threadIdx.x;
    if (i < N_NODES * NREL) g_cnt[i] = 0;
    if (i < N_NODES) g_cur[i] = 0;
}
__device__ __forceinline__ int clampi(int v, int hi) {
    v = v < 0 ? 0 : v;
    return v >= hi ? hi - 1 : v;
}
__global__ void count_kernel(const int* __restrict__ ei, const int* __restrict__ et) {
    int e = blockIdx.x * blockDim.x + threadIdx.x;
    if (e >= N_EDGES) return;
    atomicAdd(&g_cnt[clampi(ei[N_EDGES + e], N_NODES) * NREL + clampi(et[e], NREL)], 1);
}

// ---- 2-phase parallel exclusive scan: per-block scan -> (fused) bsum scan + add ----
__global__ void scan_a_kernel() {
    __shared__ int wsum[32];
    const int tid = threadIdx.x;
    const int lane = tid & 31, w = tid >> 5;
    int i = blockIdx.x * 1024 + tid;
    int v = (i < N_NODES) ? (g_cnt[i * NREL] + g_cnt[i * NREL + 1]) : 0;
    int incl = v;
#pragma unroll
    for (int o = 1; o < 32; o <<= 1) {
        int n = __shfl_up_sync(0xFFFFFFFF, incl, o);
        if (lane >= o) incl += n;
    }
    if (lane == 31) wsum[w] = incl;
    __syncthreads();
    if (w == 0) {
        int s = wsum[lane];
#pragma unroll
        for (int o = 1; o < 32; o <<= 1) {
            int n = __shfl_up_sync(0xFFFFFFFF, s, o);
            if (lane >= o) s += n;
        }
        wsum[lane] = s;
    }
    __syncthreads();
    int excl = incl - v + (w > 0 ? wsum[w - 1] : 0);
    if (i < N_NODES) g_off[i] = excl;
    if (tid == 1023) g_bsum[blockIdx.x] = wsum[31];
}
// each block redundantly scans the 49 block sums in-smem, then adds its prefix
__global__ void scan_c_kernel() {
    __shared__ int pre[64];
    const int tid = threadIdx.x;
    if (tid < 64) {
        int v = (tid < NB) ? g_bsum[tid] : 0;
        int lane = tid & 31, w2 = tid >> 5;
        int incl = v;
#pragma unroll
        for (int o = 1; o < 32; o <<= 1) {
            int n = __shfl_up_sync(0xFFFFFFFF, incl, o);
            if (lane >= o) incl += n;
        }
        pre[tid] = incl - v;        // exclusive within warp
        if (w2 == 1) pre[tid] += __shfl_sync(0xFFFFFFFF, incl, 31, 32); // wrong lane source fixed below
    }
    __syncthreads();
    // fix cross-warp carry: warp1 entries need total of warp0 (= pre[31] + bsum[31])
    if (tid == 0) {
        int c = pre[31] + ((31 < NB) ? g_bsum[31] : 0);
        pre[63] = c;   // stash carry
    }
    __syncthreads();
    int prefix;
    if (tid < 64) {
        prefix = pre[tid];
        // recompute cleanly for warp 1: exclusive scan of [32..] plus carry
    }
    // Simpler correct path: thread 0 serially scans into pre (49 elems, trivial)
    __syncthreads();
    if (tid == 0) {
        int acc = 0;
        for (int b = 0; b < NB; b++) {
            int v = g_bsum[b];
            pre[b] = acc;
            acc += v;
        }
        pre[NB] = acc;
    }
    __syncthreads();
    int i = blockIdx.x * 1024 + tid;
    if (i < N_NODES) g_off[i] += pre[blockIdx.x];
    if (blockIdx.x == 0 && tid == 0) g_off[N_NODES] = pre[NB];
}

__global__ void permute_kernel(const int* __restrict__ ei, const int* __restrict__ et) {
    int e = blockIdx.x * blockDim.x + threadIdx.x;
    if (e >= N_EDGES) return;
    int src = clampi(ei[e], N_NODES);
    int dst = clampi(ei[N_EDGES + e], N_NODES);
    int r   = clampi(et[e], NREL);
    int slot = g_off[dst] + atomicAdd(&g_cur[dst], 1);
    g_psrc[slot] = src * XD;
    int c = g_cnt[dst * NREL + r];
    float s = 1.0f / (float)(c > 0 ? c : 1);
    g_pscale[slot] = (r == 0) ? s : -s;
}

// ---------------- input convert (layer 1): emb -> x buffer 0 ----------------
__global__ void convert_x_kernel(const float* __restrict__ ext) {
    size_t i2 = ((size_t)blockIdx.x * blockDim.x + threadIdx.x) * 2;
    if (i2 >= (size_t)N_NODES * XD) return;
    float2 v = *(const float2*)(ext + i2);
    __half2 h;
    h.x = __float2half_rn(v.x);
    h.y = __float2half_rn(v.y);
    *(__half2*)&g_x[0][i2] = h;
}

// ---------------- weight build: fp16, [layer][n][kcat] ----------------
__global__ void convert_w_kernel(const float* __restrict__ W1, const float* __restrict__ r1,
                                 const float* __restrict__ W2, const float* __restrict__ r2,
                                 const float* __restrict__ W3, const float* __restrict__ r3) {
    size_t i = (size_t)blockIdx.x * blockDim.x + threadIdx.x;
    if (i >= (size_t)3 * DIM * LK) return;
    int L = (int)(i / (DIM * LK));
    int rem = (int)(i % (DIM * LK));
    int n = rem / LK, k = rem % LK;
    const float* root = (L == 0) ? r1 : (L == 1) ? r2 : r3;
    const float* Wr   = (L == 0) ? W1 : (L == 1) ? W2 : W3;
    float v;
    if (k < DIM) v = root[(size_t)k * DIM + n];
    else {
        int r = (k - DIM) / DIM, kk = (k - DIM) % DIM;
        v = Wr[(size_t)r * DIM * DIM + (size_t)kk * DIM + n];
    }
    g_wt[i] = __float2half_rn(v);
}

// ---------------- CSR gather (4-edge ILP): agg from x[xsel] -> g_agg ----------------
__global__ __launch_bounds__(96) void gather_kernel(int xsel)
{
    const int d = blockIdx.x;
    const int c = threadIdx.x * 4;
    const int beg = g_off[d], end = g_off[d + 1];
    const __half* x = g_x[xsel];

    float4 a0 = make_float4(0.f, 0.f, 0.f, 0.f);
    float4 a1 = make_float4(0.f, 0.f, 0.f, 0.f);
    int j = beg;
    for (; j + 3 < end; j += 4) {
        float s0 = g_pscale[j],     s1 = g_pscale[j + 1];
        float s2 = g_pscale[j + 2], s3 = g_pscale[j + 3];
        int o0 = g_psrc[j] + c,     o1 = g_psrc[j + 1] + c;
        int o2 = g_psrc[j + 2] + c, o3 = g_psrc[j + 3] + c;
        __half2 p00 = *(const __half2*)(x + o0), p01 = *(const __half2*)(x + o0 + 2);
        __half2 p10 = *(const __half2*)(x + o1), p11 = *(const __half2*)(x + o1 + 2);
        __half2 p20 = *(const __half2*)(x + o2), p21 = *(const __half2*)(x + o2 + 2);
        __half2 p30 = *(const __half2*)(x + o3), p31 = *(const __half2*)(x + o3 + 2);
        {
            float2 f0 = __half22float2(p00), f1 = __half22float2(p01);
            if (s0 > 0.f) { a0.x += s0 * f0.x; a0.y += s0 * f0.y; a0.z += s0 * f1.x; a0.w += s0 * f1.y; }
            else          { a1.x -= s0 * f0.x; a1.y -= s0 * f0.y; a1.z -= s0 * f1.x; a1.w -= s0 * f1.y; }
        }
        {
            float2 f0 = __half22float2(p10), f1 = __half22float2(p11);
            if (s1 > 0.f) { a0.x += s1 * f0.x; a0.y += s1 * f0.y; a0.z += s1 * f1.x; a0.w += s1 * f1.y; }
            else          { a1.x -= s1 * f0.x; a1.y -= s1 * f0.y; a1.z -= s1 * f1.x; a1.w -= s1 * f1.y; }
        }
        {
            float2 f0 = __half22float2(p20), f1 = __half22float2(p21);
            if (s2 > 0.f) { a0.x += s2 * f0.x; a0.y += s2 * f0.y; a0.z += s2 * f1.x; a0.w += s2 * f1.y; }
            else          { a1.x -= s2 * f0.x; a1.y -= s2 * f0.y; a1.z -= s2 * f1.x; a1.w -= s2 * f1.y; }
        }
        {
            float2 f0 = __half22float2(p30), f1 = __half22float2(p31);
            if (s3 > 0.f) { a0.x += s3 * f0.x; a0.y += s3 * f0.y; a0.z += s3 * f1.x; a0.w += s3 * f1.y; }
            else          { a1.x -= s3 * f0.x; a1.y -= s3 * f0.y; a1.z -= s3 * f1.x; a1.w -= s3 * f1.y; }
        }
    }
    for (; j < end; j++)
        edge_acc(x, g_pscale[j], g_psrc[j] + c, a0, a1);

    const size_t base = (size_t)d * AGD;
    __half2 o;
    o.x = __float2half_rn(a0.x); o.y = __float2half_rn(a0.y);
    *(__half2*)(g_agg + base + c) = o;
    o.x = __float2half_rn(a0.z); o.y = __float2half_rn(a0.w);
    *(__half2*)(g_agg + base + c + 2) = o;
    o.x = __float2half_rn(a1.x); o.y = __float2half_rn(a1.y);
    *(__half2*)(g_agg + base + XD + c) = o;
    o.x = __float2half_rn(a1.z); o.y = __float2half_rn(a1.w);
    *(__half2*)(g_agg + base + XD + c + 2) = o;
}

// ---------------- pipelined fp16 GEMM over logical K=1152, grid (MTILES, 3) ----------------
__device__ __forceinline__ void issue_chunk(
    uint32_t sb, int xsel, const __half* __restrict__ wt,
    int row0, int n0, int k0, int tid)
{
    const bool in_x = (k0 < XD);
    const __half* a = in_x ? g_x[xsel] : g_agg;
    const int astride = in_x ? XD : AGD;
    const int ak0 = in_x ? k0 : k0 - XD;
#pragma unroll
    for (int i = 0; i < 8; i++) {
        int u = tid + i * 256;
        int buf = u >> 10;           // 0: A, 1: B
        int rem = u & 1023;
        int row = rem >> 3;
        int c8  = (rem & 7) * 8;
        const __half* src = buf
            ? wt + (size_t)(n0 + row) * LK + k0 + c8
            : a + (size_t)(row0 + row) * astride + ak0 + c8;
        uint32_t dst = sb + buf * ST_B + row * PRB + c8 * 2;
        CP_ASYNC16(dst, src);
    }
    CP_COMMIT();
}

__global__ __launch_bounds__(256, 2) void gemm_mma_kernel(
    int layer, int xsel, const float* __restrict__ bias,
    float* __restrict__ dout, int last)
{
    extern __shared__ char smem[];
    const uint32_t sbase = smem_u32(smem);
    const int tid = threadIdx.x;
    const int wid = tid >> 5, lane = tid & 31;
    const int row0 = blockIdx.x * TM;
    const int n0 = blockIdx.y * TN;

    const __half* wt = g_wt + (size_t)layer * DIM * LK;

    const int wr = (wid >> 1) * 32;
    const int wc = (wid & 1) * 64;
    const int lrow = lane & 15;
    const int lcol8 = (lane >> 4) * 8;

    float acc[64];
#pragma unroll
    for (int i = 0; i < 64; i++) acc[i] = 0.0f;

    issue_chunk(sbase, xsel, wt, row0, n0, 0, tid);

    for (int c = 0; c < NCHUNK; c++) {
        if (c + 1 < NCHUNK) {
            issue_chunk(sbase + ((c + 1) & 1) * STAGE_BYTES, xsel, wt,
                        row0, n0, (c + 1) * KC, tid);
            CP_WAIT1();
        } else {
            CP_WAIT0();
        }
        __syncthreads();

        const uint32_t stg = sbase + (c & 1) * STAGE_BYTES;
#pragma unroll
        for (int ks = 0; ks < 4; ks++) {
            const int kb = (ks * 16 + lcol8) * 2;
            uint32_t a2[2][4], b4[4][4];
#pragma unroll
            for (int mt = 0; mt < 2; mt++)
                LDSM_X4(a2[mt], stg + ST_A + (wr + mt * 16 + lrow) * PRB + kb);
#pragma unroll
            for (int g = 0; g < 4; g++)
                LDSM_X4(b4[g], stg + ST_B + (wc + g * 16 + lrow) * PRB + kb);
#pragma unroll
            for (int mt = 0; mt < 2; mt++)
#pragma unroll
                for (int g = 0; g < 4; g++) {
                    float* d0 = &acc[((mt * 4 + g) * 2 + 0) * 4];
                    float* d1 = &acc[((mt * 4 + g) * 2 + 1) * 4];
                    mma16816(d0, a2[mt], b4[g][0], b4[g][2]);
                    mma16816(d1, a2[mt], b4[g][1], b4[g][3]);
                }
        }
        __syncthreads();
    }

    // ---- epilogue: +bias; non-last: relu + fp16 into x[xsel^1]; last: fp32 dout ----
    const int qr = lane >> 2, qc = (lane & 3) * 2;
    __half* ox = g_x[xsel ^ 1];
#pragma unroll
    for (int mt = 0; mt < 2; mt++) {
#pragma unroll
        for (int nt = 0; nt < 8; nt++) {
            const float* d = &acc[((mt * 4 + (nt >> 1)) * 2 + (nt & 1)) * 4];
            int m0 = row0 + wr + mt * 16 + qr;
            int n = n0 + wc + (nt >> 1) * 16 + (nt & 1) * 8 + qc;
            float2 bb = *(const float2*)(bias + n);
#pragma unroll
            for (int h = 0; h < 2; h++) {
                int m = m0 + h * 8;
                if (m >= N_NODES) continue;
                float x = d[h * 2 + 0] + bb.x;
                float y = d[h * 2 + 1] + bb.y;
                if (last) {
                    *(float2*)(dout + (size_t)m * DIM + n) = make_float2(x, y);
                } else {
                    __half2 o;
                    o.x = __float2half_rn(fmaxf(x, 0.f));
                    o.y = __float2half_rn(fmaxf(y, 0.f));
                    *(__half2*)(ox + (size_t)m * XD + n) = o;
                }
            }
        }
    }
}

// ---------------- launch ----------------
extern "C" void kernel_launch(void* const* d_in, const int* in_sizes, int n_in,
                              void* d_out, int out_size)
{
    const float* emb = (const float*)d_in[0];
    const int*   ei  = (const int*)d_in[1];
    const int*   et  = (const int*)d_in[2];
    const float* W1 = (const float*)d_in[3];
    const float* r1 = (const float*)d_in[4];
    const float* b1 = (const float*)d_in[5];
    const float* W2 = (const float*)d_in[6];
    const float* r2 = (const float*)d_in[7];
    const float* b2 = (const float*)d_in[8];
    const float* W3 = (const float*)d_in[9];
    const float* r3 = (const float*)d_in[10];
    const float* b3 = (const float*)d_in[11];
    float* out = (float*)d_out;

    cudaFuncSetAttribute(gemm_mma_kernel,
                         cudaFuncAttributeMaxDynamicSharedMemorySize, SMEM_TOTAL);

    zero_kernel<<<(N_NODES * NREL + 255) / 256, 256>>>();
    count_kernel<<<(N_EDGES + 255) / 256, 256>>>(ei, et);
    scan_a_kernel<<<NB, 1024>>>();
    scan_c_kernel<<<NB, 1024>>>();
    permute_kernel<<<(N_EDGES + 255) / 256, 256>>>(ei, et);
    convert_w_kernel<<<(int)(((size_t)3 * DIM * LK + 255) / 256), 256>>>(W1, r1, W2, r2, W3, r3);

    dim3 ggrid(MTILES, 3);
    int cv_blocks = (int)(((size_t)N_NODES * XD / 2 + 255) / 256);

    convert_x_kernel<<<cv_blocks, 256>>>(emb);
    // layer 1: x[0] -> x[1]
    gather_kernel<<<N_NODES, 96>>>(0);
    gemm_mma_kernel<<<ggrid, 256, SMEM_TOTAL>>>(0, 0, b1, out, 0);
    // layer 2: x[1] -> x[0]
    gather_kernel<<<N_NODES, 96>>>(1);
    gemm_mma_kernel<<<ggrid, 256, SMEM_TOTAL>>>(1, 1, b2, out, 0);
    // layer 3: x[0] -> dout
    gather_kernel<<<N_NODES, 96>>>(0);
    gemm_mma_kernel<<<ggrid, 256, SMEM_TOTAL>>>(2, 0, b3, out, 1);
}